// round 3
// baseline (speedup 1.0000x reference)
#include <cuda_runtime.h>
#include <cstdint>

// Problem constants (shapes fixed by the reference: B=4, S=4096, H=4096, E=64, K=2)
#define HDIM 4096
#define EXP  64
#define HC   64            // K-chunk staged per iteration
#define TOK_PER_BLK 128
#define NTHREADS 256
#define XS_STRIDE 68       // token-major x tile stride (floats), 16B aligned rows
#define WS_STRIDE 68       // k-major w tile stride (floats), 16B aligned rows

__device__ float g_partials[512];

// Packed fp32x2 FMA (Blackwell FFMA2) — 2x fp32 throughput vs scalar FFMA.
__device__ __forceinline__ unsigned long long ffma2(unsigned long long a,
                                                    unsigned long long b,
                                                    unsigned long long c) {
    unsigned long long d;
    asm("fma.rn.f32x2 %0, %1, %2, %3;" : "=l"(d) : "l"(a), "l"(b), "l"(c));
    return d;
}
__device__ __forceinline__ unsigned long long dupf(float x) {
    unsigned long long r;
    asm("mov.b64 %0, {%1, %1};" : "=l"(r) : "f"(x));
    return r;
}

extern __shared__ float sm[];

// Fused router: GEMM (128 tok x 64 exp x 4096) + softmax + top-2 + z_loss partial.
__global__ __launch_bounds__(NTHREADS) void router_kernel(
    const float* __restrict__ x,     // [T, HDIM]
    const float* __restrict__ gw,    // [EXP, HDIM]
    float* __restrict__ out,         // [2T idx | 2T scores | aux | z]
    int T)
{
    float* xs = sm;                                // [128][XS_STRIDE] token-major
    float* ws = sm + TOK_PER_BLK * XS_STRIDE;      // [HC][WS_STRIDE]  k-major

    const int tid  = threadIdx.x;
    const int te   = tid & 7;          // expert-thread: experts te*8 .. te*8+7
    const int tty  = tid >> 3;         // token-thread: tokens tty*4 .. tty*4+3
    const int tok0 = blockIdx.x * TOK_PER_BLK;

    // staging coords
    const int kq = tid & 15;           // 16 threads cover 64 k (float4 each)
    const int rr = tid >> 4;           // 0..15

    // 4 tokens x 4 expert-pairs packed accumulators (= 4x8 fp32)
    unsigned long long acc[4][4];
    #pragma unroll
    for (int a = 0; a < 4; ++a)
        #pragma unroll
        for (int b = 0; b < 4; ++b) acc[a][b] = 0ull;

    for (int k0 = 0; k0 < HDIM; k0 += HC) {
        __syncthreads();   // protect previous tile reads

        // stage x: 128 tok x 64 k, coalesced along k (lanes = consecutive kq)
        #pragma unroll
        for (int i = 0; i < 8; ++i) {
            int tok = rr * 8 + i;
            float4 v = *reinterpret_cast<const float4*>(
                &x[(size_t)(tok0 + tok) * HDIM + k0 + kq * 4]);
            *reinterpret_cast<float4*>(&xs[tok * XS_STRIDE + kq * 4]) = v;
        }
        // stage w transposed to k-major so expert pairs are contiguous b64s
        #pragma unroll
        for (int i = 0; i < 4; ++i) {
            int e = rr * 4 + i;
            float4 v = *reinterpret_cast<const float4*>(
                &gw[(size_t)e * HDIM + k0 + kq * 4]);
            ws[(kq * 4 + 0) * WS_STRIDE + e] = v.x;
            ws[(kq * 4 + 1) * WS_STRIDE + e] = v.y;
            ws[(kq * 4 + 2) * WS_STRIDE + e] = v.z;
            ws[(kq * 4 + 3) * WS_STRIDE + e] = v.w;
        }
        __syncthreads();

        // compute: HC k-steps in quads
        #pragma unroll 4
        for (int q = 0; q < HC / 4; ++q) {
            const int kk = q * 4;
            float4 xq[4];
            #pragma unroll
            for (int tt = 0; tt < 4; ++tt)
                xq[tt] = *reinterpret_cast<const float4*>(
                    &xs[(tty * 4 + tt) * XS_STRIDE + kk]);

            #pragma unroll
            for (int j = 0; j < 4; ++j) {
                const ulonglong2* wp = reinterpret_cast<const ulonglong2*>(
                    &ws[(kk + j) * WS_STRIDE + te * 8]);
                ulonglong2 wa = wp[0];
                ulonglong2 wb = wp[1];
                #pragma unroll
                for (int tt = 0; tt < 4; ++tt) {
                    unsigned long long x2 =
                        dupf(reinterpret_cast<const float*>(&xq[tt])[j]);
                    acc[tt][0] = ffma2(wa.x, x2, acc[tt][0]);
                    acc[tt][1] = ffma2(wa.y, x2, acc[tt][1]);
                    acc[tt][2] = ffma2(wb.x, x2, acc[tt][2]);
                    acc[tt][3] = ffma2(wb.y, x2, acc[tt][3]);
                }
            }
        }
    }

    // ---- epilogue: logits -> smem (stride 66, reuse xs region) ----
    __syncthreads();
    float* ls = sm;  // 128 * 66 floats = 33792B <= xs region 34816B
    #pragma unroll
    for (int tt = 0; tt < 4; ++tt) {
        int t = tty * 4 + tt;
        #pragma unroll
        for (int p = 0; p < 4; ++p) {
            float2 v = *reinterpret_cast<float2*>(&acc[tt][p]);
            *reinterpret_cast<float2*>(&ls[t * 66 + te * 8 + p * 2]) = v;
        }
    }
    __syncthreads();

    float zsum = 0.f;
    if (tid < TOK_PER_BLK) {
        const float* row = &ls[tid * 66];
        // top-1 (strict > keeps lowest index on ties, matching lax.top_k)
        float m = -3.402823466e38f; int i1 = 0;
        #pragma unroll 8
        for (int e = 0; e < EXP; ++e) {
            float v = row[e];
            if (v > m) { m = v; i1 = e; }
        }
        // top-2 excluding i1
        float m2 = -3.402823466e38f; int i2 = 0;
        #pragma unroll 8
        for (int e = 0; e < EXP; ++e) {
            if (e == i1) continue;
            float v = row[e];
            if (v > m2) { m2 = v; i2 = e; }
        }
        // softmax normalizer + z_loss partial
        float Z = 0.f;
        #pragma unroll 8
        for (int e = 0; e < EXP; ++e) {
            float v = row[e];
            Z += expf(v - m);
            zsum += v * v;
        }
        int g = tok0 + tid;
        out[2 * g]     = (float)i1;
        out[2 * g + 1] = (float)i2;
        out[2 * T + 2 * g]     = 1.0f / Z;           // exp(m-m)/Z
        out[2 * T + 2 * g + 1] = expf(m2 - m) / Z;
    }

    // deterministic block reduce of z partial
    __shared__ float zred[NTHREADS];
    zred[tid] = zsum;
    __syncthreads();
    #pragma unroll
    for (int s = NTHREADS / 2; s > 0; s >>= 1) {
        if (tid < s) zred[tid] += zred[tid + s];
        __syncthreads();
    }
    if (tid == 0) g_partials[blockIdx.x] = zred[0];
}

__global__ void finalize_kernel(float* __restrict__ out, int nblk, int T) {
    __shared__ float s[256];
    int tid = threadIdx.x;
    s[tid] = (tid < nblk) ? g_partials[tid] : 0.f;
    __syncthreads();
    #pragma unroll
    for (int st = 128; st > 0; st >>= 1) {
        if (tid < st) s[tid] += s[tid + st];
        __syncthreads();
    }
    if (tid == 0) {
        out[4 * T]     = 0.0f;                          // aux_loss
        out[4 * T + 1] = s[0] / (float)(T * EXP);       // z_loss
    }
}

extern "C" void kernel_launch(void* const* d_in, const int* in_sizes, int n_in,
                              void* d_out, int out_size) {
    const float* x  = (const float*)d_in[0];
    const float* gw = (const float*)d_in[1];
    float* out = (float*)d_out;

    int T = in_sizes[0] / HDIM;          // 16384 tokens
    int blocks = T / TOK_PER_BLK;        // 128

    size_t smem = (size_t)(TOK_PER_BLK * XS_STRIDE + HC * WS_STRIDE) * sizeof(float); // 52224B
    cudaFuncSetAttribute(router_kernel,
                         cudaFuncAttributeMaxDynamicSharedMemorySize, (int)smem);

    router_kernel<<<blocks, NTHREADS, smem>>>(x, gw, out, T);
    finalize_kernel<<<1, 256>>>(out, blocks, T);
}

// round 4
// speedup vs baseline: 1.8628x; 1.8628x over previous
#include <cuda_runtime.h>
#include <cstdint>

// B=4, S=4096, H=4096, E=64, K=2  ->  T=16384 tokens
#define HDIM 4096
#define EXP  64
#define HC   64              // K-chunk per pipeline stage
#define TOK_PER_BLK 128
#define NTHREADS 128
#define XS_STRIDE 72         // x tile row stride (floats): warp rows hit banks 0/8/16/24
#define X_TILE (TOK_PER_BLK * XS_STRIDE)   // 9216 floats
#define W_TILE (HC * EXP)                  // 4096 floats (row = 64 floats, bank-clean)
#define BUF_FLOATS (X_TILE + W_TILE)       // 13312 floats = 53248 B per buffer

__device__ float g_partials[512];
__device__ float g_wT[HDIM * EXP];         // gate_w transposed: [k][e]

// Packed fp32x2 FMA (Blackwell FFMA2) — 2 fp32 FMAs per instruction.
__device__ __forceinline__ unsigned long long ffma2(unsigned long long a,
                                                    unsigned long long b,
                                                    unsigned long long c) {
    unsigned long long d;
    asm("fma.rn.f32x2 %0, %1, %2, %3;" : "=l"(d) : "l"(a), "l"(b), "l"(c));
    return d;
}
__device__ __forceinline__ unsigned long long dupf(float x) {
    unsigned long long r;
    asm("mov.b64 %0, {%1, %1};" : "=l"(r) : "f"(x));
    return r;
}
__device__ __forceinline__ void cp16(void* dst, const void* src) {
    unsigned d = (unsigned)__cvta_generic_to_shared(dst);
    asm volatile("cp.async.cg.shared.global [%0], [%1], 16;" :: "r"(d), "l"(src));
}
__device__ __forceinline__ void cp_commit() {
    asm volatile("cp.async.commit_group;");
}
__device__ __forceinline__ void cp_wait0() {
    asm volatile("cp.async.wait_group 0;");
}

extern __shared__ float sm[];

// ---- one-time gate_w transpose: gw[64][4096] -> g_wT[4096][64] ----
__global__ void transpose_w(const float* __restrict__ gw) {
    __shared__ float t[64][65];
    const int k0 = blockIdx.x * 64;
    const int tid = threadIdx.x;      // 256 threads
    #pragma unroll
    for (int i = 0; i < 4; ++i) {
        int lin = i * 256 + tid;      // float4 units in 64x64 tile
        int e = lin >> 4, kq = lin & 15;
        float4 v = *reinterpret_cast<const float4*>(&gw[(size_t)e * HDIM + k0 + kq * 4]);
        t[e][kq * 4 + 0] = v.x; t[e][kq * 4 + 1] = v.y;
        t[e][kq * 4 + 2] = v.z; t[e][kq * 4 + 3] = v.w;
    }
    __syncthreads();
    #pragma unroll
    for (int i = 0; i < 4; ++i) {
        int lin = i * 256 + tid;
        int k = lin >> 4, eq = lin & 15;
        float4 v;
        v.x = t[eq * 4 + 0][k]; v.y = t[eq * 4 + 1][k];
        v.z = t[eq * 4 + 2][k]; v.w = t[eq * 4 + 3][k];
        *reinterpret_cast<float4*>(&g_wT[(size_t)(k0 + k) * EXP + eq * 4]) = v;
    }
}

// stage one K-chunk: x (token-major) + wT (k-major) into smem buffer via cp.async
__device__ __forceinline__ void stage_chunk(float* xs, float* ws,
                                            const float* __restrict__ x,
                                            int tok0, int k0, int tid) {
    #pragma unroll
    for (int i = 0; i < 16; ++i) {
        int lin = i * NTHREADS + tid;
        int tok = lin >> 4, kq = lin & 15;
        cp16(&xs[tok * XS_STRIDE + kq * 4],
             &x[(size_t)(tok0 + tok) * HDIM + k0 + kq * 4]);
    }
    #pragma unroll
    for (int i = 0; i < 8; ++i) {
        int lin = i * NTHREADS + tid;
        cp16(&ws[lin * 4], &g_wT[(size_t)k0 * EXP + lin * 4]);
    }
    cp_commit();
}

__global__ __launch_bounds__(NTHREADS) void router_kernel(
    const float* __restrict__ x,     // [T, HDIM]
    float* __restrict__ out,         // [2T idx | 2T scores | aux | z]
    int T)
{
    const int tid  = threadIdx.x;
    const int te   = tid & 7;         // expert group: {te*4..+3} and {te*4+32..+35}
    const int tty  = tid >> 3;        // tokens tty + 16*i, i=0..7
    const int tok0 = blockIdx.x * TOK_PER_BLK;

    // 8 tokens x 8 experts = 8 x 4 packed f32x2 accumulators
    unsigned long long acc[8][4];
    #pragma unroll
    for (int t = 0; t < 8; ++t)
        #pragma unroll
        for (int p = 0; p < 4; ++p) acc[t][p] = 0ull;

    // prologue: stage chunk 0
    stage_chunk(sm, sm + X_TILE, x, tok0, 0, tid);
    cp_wait0();
    __syncthreads();

    for (int c = 0; c < HDIM / HC; ++c) {
        float* xs = sm + (c & 1) * BUF_FLOATS;
        float* ws = xs + X_TILE;
        if (c + 1 < HDIM / HC)
            stage_chunk(sm + ((c + 1) & 1) * BUF_FLOATS,
                        sm + ((c + 1) & 1) * BUF_FLOATS + X_TILE,
                        x, tok0, (c + 1) * HC, tid);

        #pragma unroll 2
        for (int q = 0; q < HC / 4; ++q) {
            float4 xv[8];
            #pragma unroll
            for (int t = 0; t < 8; ++t)
                xv[t] = *reinterpret_cast<const float4*>(
                    &xs[(tty + 16 * t) * XS_STRIDE + q * 4]);
            #pragma unroll
            for (int j = 0; j < 4; ++j) {
                const ulonglong2 wa = *reinterpret_cast<const ulonglong2*>(
                    &ws[(q * 4 + j) * EXP + te * 4]);          // experts te*4..+3
                const ulonglong2 wb = *reinterpret_cast<const ulonglong2*>(
                    &ws[(q * 4 + j) * EXP + 32 + te * 4]);     // experts te*4+32..+35
                #pragma unroll
                for (int t = 0; t < 8; ++t) {
                    unsigned long long x2 =
                        dupf(reinterpret_cast<const float*>(&xv[t])[j]);
                    acc[t][0] = ffma2(wa.x, x2, acc[t][0]);
                    acc[t][1] = ffma2(wa.y, x2, acc[t][1]);
                    acc[t][2] = ffma2(wb.x, x2, acc[t][2]);
                    acc[t][3] = ffma2(wb.y, x2, acc[t][3]);
                }
            }
        }
        cp_wait0();
        __syncthreads();
    }

    // ---- epilogue: logits -> smem [128][66] ----
    float* ls = sm;   // 8448 floats, fits in buffer 0
    __syncthreads();
    #pragma unroll
    for (int t = 0; t < 8; ++t) {
        float* row = &ls[(tty + 16 * t) * 66];
        *reinterpret_cast<float2*>(&row[te * 4])      = *reinterpret_cast<float2*>(&acc[t][0]);
        *reinterpret_cast<float2*>(&row[te * 4 + 2])  = *reinterpret_cast<float2*>(&acc[t][1]);
        *reinterpret_cast<float2*>(&row[te * 4 + 32]) = *reinterpret_cast<float2*>(&acc[t][2]);
        *reinterpret_cast<float2*>(&row[te * 4 + 34]) = *reinterpret_cast<float2*>(&acc[t][3]);
    }
    __syncthreads();

    // one thread per token: top-2 + softmax scores + z partial
    float zsum = 0.f;
    {
        const float* row = &ls[tid * 66];
        float m = -3.402823466e38f; int i1 = 0;
        #pragma unroll 8
        for (int e = 0; e < EXP; ++e) {
            float v = row[e];
            if (v > m) { m = v; i1 = e; }
        }
        float m2 = -3.402823466e38f; int i2 = 0;
        #pragma unroll 8
        for (int e = 0; e < EXP; ++e) {
            if (e == i1) continue;
            float v = row[e];
            if (v > m2) { m2 = v; i2 = e; }
        }
        float Z = 0.f;
        #pragma unroll 8
        for (int e = 0; e < EXP; ++e) {
            float v = row[e];
            Z += expf(v - m);
            zsum += v * v;
        }
        int g = tok0 + tid;
        out[2 * g]     = (float)i1;
        out[2 * g + 1] = (float)i2;
        out[2 * T + 2 * g]     = 1.0f / Z;
        out[2 * T + 2 * g + 1] = expf(m2 - m) / Z;
    }

    // deterministic block reduce of z partial
    __shared__ float zred[NTHREADS];
    zred[tid] = zsum;
    __syncthreads();
    #pragma unroll
    for (int s = NTHREADS / 2; s > 0; s >>= 1) {
        if (tid < s) zred[tid] += zred[tid + s];
        __syncthreads();
    }
    if (tid == 0) g_partials[blockIdx.x] = zred[0];
}

__global__ void finalize_kernel(float* __restrict__ out, int nblk, int T) {
    __shared__ float s[256];
    int tid = threadIdx.x;
    s[tid] = (tid < nblk) ? g_partials[tid] : 0.f;
    __syncthreads();
    #pragma unroll
    for (int st = 128; st > 0; st >>= 1) {
        if (tid < st) s[tid] += s[tid + st];
        __syncthreads();
    }
    if (tid == 0) {
        out[4 * T]     = 0.0f;                       // aux_loss
        out[4 * T + 1] = s[0] / (float)(T * EXP);    // z_loss
    }
}

extern "C" void kernel_launch(void* const* d_in, const int* in_sizes, int n_in,
                              void* d_out, int out_size) {
    const float* x  = (const float*)d_in[0];
    const float* gw = (const float*)d_in[1];
    float* out = (float*)d_out;

    int T = in_sizes[0] / HDIM;           // 16384
    int blocks = T / TOK_PER_BLK;         // 128

    size_t smem = 2 * BUF_FLOATS * sizeof(float);   // 106496 B
    cudaFuncSetAttribute(router_kernel,
                         cudaFuncAttributeMaxDynamicSharedMemorySize, (int)smem);

    transpose_w<<<HDIM / 64, 256>>>(gw);
    router_kernel<<<blocks, NTHREADS, smem>>>(x, out, T);
    finalize_kernel<<<1, 256>>>(out, blocks, T);
}

// round 8
// speedup vs baseline: 2.8268x; 1.5175x over previous
#include <cuda_runtime.h>
#include <cuda_bf16.h>
#include <cstdint>

// B=4, S=4096, H=4096, E=64, topK=2 -> T=16384 tokens
#define HDIM 4096
#define EXP  64
#define HC   64                       // K per pipeline chunk
#define NCHUNKS (HDIM / HC)           // 64
#define TOK_PER_BLK 128
#define NTHREADS 256                  // warps 0-3 consumers, 4-7 producers

#define A_SPLIT 16384                 // 128 rows x 128 B (64 bf16) SW128
#define B_SPLIT 8192                  // 64 rows x 128 B SW128
#define A_REGION (3 * A_SPLIT)        // 49152
#define B_REGION (3 * B_SPLIT)        // 24576
#define W_CHUNK_BYTES B_REGION
#define BUF_BYTES (A_REGION + B_REGION)       // 73728
#define SMEM_TOTAL (2 * BUF_BYTES)            // 147456

__device__ float g_partials[512];
__device__ unsigned char g_w_sw[NCHUNKS * W_CHUNK_BYTES]; // 1.5 MB, L2-resident

// ---------------- helpers ----------------
__device__ __forceinline__ unsigned sw128(unsigned off) {
    return off ^ ((off >> 3) & 0x70);
}
// pack 2 fp32 -> bf16x2 (lo half = first arg)
__device__ __forceinline__ uint32_t bf2(float lo, float hi) {
    uint32_t r;
    asm("cvt.rn.bf16x2.f32 %0, %1, %2;" : "=r"(r) : "f"(hi), "f"(lo));
    return r;
}
__device__ __forceinline__ void cp16s(uint32_t dst, const void* src) {
    asm volatile("cp.async.cg.shared.global [%0], [%1], 16;" :: "r"(dst), "l"(src));
}
__device__ __forceinline__ void cp_commit() { asm volatile("cp.async.commit_group;"); }
__device__ __forceinline__ void cp_wait0()  { asm volatile("cp.async.wait_group 0;"); }

__device__ __forceinline__ void ldm4(uint32_t& r0, uint32_t& r1, uint32_t& r2,
                                     uint32_t& r3, uint32_t addr) {
    asm volatile("ldmatrix.sync.aligned.m8n8.x4.shared.b16 {%0,%1,%2,%3}, [%4];"
                 : "=r"(r0), "=r"(r1), "=r"(r2), "=r"(r3) : "r"(addr));
}
__device__ __forceinline__ void mma16816(float* d, const uint32_t* a, const uint32_t* b) {
    asm volatile(
        "mma.sync.aligned.m16n8k16.row.col.f32.bf16.bf16.f32 "
        "{%0,%1,%2,%3}, {%4,%5,%6,%7}, {%8,%9}, {%0,%1,%2,%3};"
        : "+f"(d[0]), "+f"(d[1]), "+f"(d[2]), "+f"(d[3])
        : "r"(a[0]), "r"(a[1]), "r"(a[2]), "r"(a[3]), "r"(b[0]), "r"(b[1]));
}

// ---------------- prologue: split+swizzle gate_w into per-chunk images ----------------
__global__ void prep_w(const float* __restrict__ gw) {
    int idx = blockIdx.x * blockDim.x + threadIdx.x;  // 64c * 64e * 32kp = 131072
    int kp = idx & 31;
    int e  = (idx >> 5) & 63;
    int c  = idx >> 11;
    float2 v = *reinterpret_cast<const float2*>(&gw[(size_t)e * HDIM + c * HC + kp * 2]);
    float ax = v.x, ay = v.y;
    unsigned off = sw128((unsigned)(e * 128 + kp * 4));
    unsigned char* base = g_w_sw + (size_t)c * W_CHUNK_BYTES;
    #pragma unroll
    for (int s = 0; s < 3; ++s) {
        uint32_t p = bf2(ax, ay);
        *reinterpret_cast<uint32_t*>(base + s * B_SPLIT + off) = p;
        ax -= __uint_as_float(p << 16);
        ay -= __uint_as_float(p & 0xFFFF0000u);
    }
}

// ---------------- producer staging ----------------
__device__ __forceinline__ void load_v(float4* v, const float* __restrict__ x,
                                       int tok0, int k0, int kq, int rbase) {
    #pragma unroll
    for (int i = 0; i < 16; ++i)
        v[i] = *reinterpret_cast<const float4*>(
            &x[(size_t)(tok0 + rbase + 8 * i) * HDIM + k0 + kq * 4]);
}
__device__ __forceinline__ void stage_x(unsigned char* buf, const float4* v,
                                        int kq, int rbase) {
    #pragma unroll
    for (int i = 0; i < 16; ++i) {
        int r = rbase + 8 * i;
        unsigned off = sw128((unsigned)(r * 128 + kq * 8));
        float ax = v[i].x, ay = v[i].y, az = v[i].z, aw = v[i].w;
        #pragma unroll
        for (int s = 0; s < 3; ++s) {
            uint32_t p0 = bf2(ax, ay);
            uint32_t p1 = bf2(az, aw);
            *reinterpret_cast<uint2*>(buf + s * A_SPLIT + off) = make_uint2(p0, p1);
            if (s < 2) {
                ax -= __uint_as_float(p0 << 16);
                ay -= __uint_as_float(p0 & 0xFFFF0000u);
                az -= __uint_as_float(p1 << 16);
                aw -= __uint_as_float(p1 & 0xFFFF0000u);
            }
        }
    }
}

// ---------------- main fused router ----------------
extern __shared__ unsigned char smem_raw[];

__global__ __launch_bounds__(NTHREADS, 1)
void router_kernel(const float* __restrict__ x, float* __restrict__ out, int T) {
    const int tid  = threadIdx.x;
    const int lane = tid & 31;
    const int tok0 = blockIdx.x * TOK_PER_BLK;
    const uint32_t sb = (uint32_t)__cvta_generic_to_shared(smem_raw);

    // producer coords (tid >= 128)
    const int ptid  = tid - 128;
    const int kq    = ptid & 15;
    const int rbase = ptid >> 4;
    float4 v[16];

    // consumer coords (tid < 128): warp cw covers m-half (cw>>1), n-half (cw&1)
    const int cw    = tid >> 5;
    const int mbase = (cw >> 1) * 64;
    const int nbase = (cw & 1) * 32;
    const int rl    = lane & 15;            // A ldmatrix local row
    const int cb    = lane >> 4;            // A kunit offset (0/1)
    const int arx   = rl & 7;
    const int browl = (lane & 7) + ((lane & 16) >> 1);  // B local row 0..15
    const int bcb   = (lane >> 3) & 1;      // B kunit offset
    const int bxor  = lane & 7;

    float acc[4][4][4];
    #pragma unroll
    for (int mt = 0; mt < 4; ++mt)
        #pragma unroll
        for (int nt = 0; nt < 4; ++nt)
            #pragma unroll
            for (int r = 0; r < 4; ++r) acc[mt][nt][r] = 0.f;

    // ---- prologue: producers stage chunk 0, prefetch chunk 1 ----
    if (tid >= 128) {
        load_v(v, x, tok0, 0, kq, rbase);
        // B chunk 0
        #pragma unroll
        for (int i = 0; i < 12; ++i) {
            int lin = i * 128 + ptid;
            cp16s(sb + A_REGION + lin * 16, g_w_sw + lin * 16);
        }
        cp_commit();
        stage_x(smem_raw, v, kq, rbase);
        load_v(v, x, tok0, HC, kq, rbase);
        cp_wait0();
    }

    for (int c = 0; c < NCHUNKS; ++c) {
        __syncthreads();
        if (tid < 128) {
            // ---- consumer: 4 ksteps x 6 split-products on buf(c&1) ----
            const uint32_t Ab = sb + (c & 1) * BUF_BYTES;
            const uint32_t Bb = Ab + A_REGION;
            const uint32_t a_row = Ab + (mbase + rl) * 128;
            const uint32_t b_row = Bb + (nbase + browl) * 128;
            #pragma unroll
            for (int ks = 0; ks < 4; ++ks) {
                uint32_t bf[3][8];
                const uint32_t bcol = (uint32_t)(((2 * ks + bcb) ^ bxor) * 16);
                #pragma unroll
                for (int s = 0; s < 3; ++s) {
                    ldm4(bf[s][0], bf[s][1], bf[s][2], bf[s][3],
                         b_row + s * B_SPLIT + bcol);            // n tiles 0,1
                    ldm4(bf[s][4], bf[s][5], bf[s][6], bf[s][7],
                         b_row + s * B_SPLIT + 2048 + bcol);     // n tiles 2,3
                }
                uint32_t af[3][4][4];
                const uint32_t acol = (uint32_t)(((2 * ks + cb) ^ arx) * 16);
                #pragma unroll
                for (int s = 0; s < 3; ++s)
                    #pragma unroll
                    for (int mt = 0; mt < 4; ++mt)
                        ldm4(af[s][mt][0], af[s][mt][1], af[s][mt][2], af[s][mt][3],
                             a_row + s * A_SPLIT + mt * 2048 + acol);
                // 6 products with split-level sum <= 3
                #pragma unroll
                for (int p = 0; p < 6; ++p) {
                    const int sa = (p == 0 || p == 1 || p == 3) ? 0 : (p == 2 || p == 5) ? 1 : 2;
                    const int sbi = (p == 0 || p == 2 || p == 4) ? 0 : (p == 1 || p == 5) ? 1 : 2;
                    #pragma unroll
                    for (int mt = 0; mt < 4; ++mt)
                        #pragma unroll
                        for (int nt = 0; nt < 4; ++nt)
                            mma16816(acc[mt][nt], af[sa][mt], &bf[sbi][nt * 2]);
                }
            }
        } else if (c + 1 < NCHUNKS) {
            // ---- producer: stage chunk c+1 into buf((c+1)&1) ----
            unsigned char* buf = smem_raw + ((c + 1) & 1) * BUF_BYTES;
            const uint32_t bufu = sb + ((c + 1) & 1) * BUF_BYTES;
            const unsigned char* src = g_w_sw + (size_t)(c + 1) * W_CHUNK_BYTES;
            #pragma unroll
            for (int i = 0; i < 12; ++i) {
                int lin = i * 128 + ptid;
                cp16s(bufu + A_REGION + lin * 16, src + lin * 16);
            }
            cp_commit();
            stage_x(buf, v, kq, rbase);
            if (c + 2 < NCHUNKS)
                load_v(v, x, tok0, (c + 2) * HC, kq, rbase);
            cp_wait0();
        }
    }

    // ---- epilogue: logits -> smem [128][68] ----
    __syncthreads();
    float* ls = reinterpret_cast<float*>(smem_raw);
    if (tid < 128) {
        #pragma unroll
        for (int mt = 0; mt < 4; ++mt) {
            int row0 = mbase + mt * 16 + (lane >> 2);
            #pragma unroll
            for (int nt = 0; nt < 4; ++nt) {
                int col = nbase + nt * 8 + (lane & 3) * 2;
                *reinterpret_cast<float2*>(&ls[row0 * 68 + col]) =
                    make_float2(acc[mt][nt][0], acc[mt][nt][1]);
                *reinterpret_cast<float2*>(&ls[(row0 + 8) * 68 + col]) =
                    make_float2(acc[mt][nt][2], acc[mt][nt][3]);
            }
        }
    }
    __syncthreads();

    // one thread per token: top-2 + softmax scores + z partial
    float zsum = 0.f;
    if (tid < 128) {
        const float* row = &ls[tid * 68];
        float m = -3.402823466e38f; int i1 = 0;
        #pragma unroll 8
        for (int e = 0; e < EXP; ++e) {
            float vv = row[e];
            if (vv > m) { m = vv; i1 = e; }
        }
        float m2 = -3.402823466e38f; int i2 = 0;
        #pragma unroll 8
        for (int e = 0; e < EXP; ++e) {
            if (e == i1) continue;
            float vv = row[e];
            if (vv > m2) { m2 = vv; i2 = e; }
        }
        float Z = 0.f;
        #pragma unroll 8
        for (int e = 0; e < EXP; ++e) {
            float vv = row[e];
            Z += expf(vv - m);
            zsum += vv * vv;
        }
        int g = tok0 + tid;
        out[2 * g]     = (float)i1;
        out[2 * g + 1] = (float)i2;
        out[2 * T + 2 * g]     = 1.0f / Z;
        out[2 * T + 2 * g + 1] = expf(m2 - m) / Z;
    }

    // deterministic block reduce of z partial
    __shared__ float zred[NTHREADS];
    zred[tid] = zsum;
    __syncthreads();
    #pragma unroll
    for (int s = NTHREADS / 2; s > 0; s >>= 1) {
        if (tid < s) zred[tid] += zred[tid + s];
        __syncthreads();
    }
    if (tid == 0) g_partials[blockIdx.x] = zred[0];
}

__global__ void finalize_kernel(float* __restrict__ out, int nblk, int T) {
    __shared__ float s[256];
    int tid = threadIdx.x;
    s[tid] = (tid < nblk) ? g_partials[tid] : 0.f;
    __syncthreads();
    #pragma unroll
    for (int st = 128; st > 0; st >>= 1) {
        if (tid < st) s[tid] += s[tid + st];
        __syncthreads();
    }
    if (tid == 0) {
        out[4 * T]     = 0.0f;                      // aux_loss
        out[4 * T + 1] = s[0] / (float)(T * EXP);   // z_loss
    }
}

extern "C" void kernel_launch(void* const* d_in, const int* in_sizes, int n_in,
                              void* d_out, int out_size) {
    const float* x  = (const float*)d_in[0];
    const float* gw = (const float*)d_in[1];
    float* out = (float*)d_out;

    int T = in_sizes[0] / HDIM;            // 16384
    int blocks = T / TOK_PER_BLK;          // 128

    cudaFuncSetAttribute(router_kernel,
                         cudaFuncAttributeMaxDynamicSharedMemorySize, SMEM_TOTAL);

    prep_w<<<512, 256>>>(gw);
    router_kernel<<<blocks, NTHREADS, SMEM_TOTAL>>>(x, out, T);
    finalize_kernel<<<1, 256>>>(out, blocks, T);
}

// round 10
// speedup vs baseline: 3.9810x; 1.4083x over previous
#include <cuda_runtime.h>
#include <cuda_fp16.h>
#include <cstdint>

// B=4, S=4096, H=4096, E=64, topK=2 -> T=16384 tokens
#define HDIM 4096
#define EXP  64
#define HC   64                        // K per pipeline chunk
#define NCHUNKS (HDIM / HC)            // 64
#define TOK_PER_BLK 128
#define NTHREADS 256                   // 8 homogeneous warps

#define A_SPLIT 16384                  // 128 rows x 128 B (64 fp16) SW128
#define B_SPLIT 8192                   // 64 rows x 128 B SW128
#define A_REGION (2 * A_SPLIT)         // 32768
#define B_REGION (2 * B_SPLIT)         // 16384
#define W_CHUNK_BYTES B_REGION
#define BUF_BYTES (A_REGION + B_REGION)        // 49152
#define SMEM_TOTAL (2 * BUF_BYTES)             // 98304

#define WSCALE 64.0f
#define INV_WSCALE 0.015625f

__device__ float g_partials[256];
__device__ unsigned int g_done;
__device__ unsigned char g_w_sw[NCHUNKS * W_CHUNK_BYTES];  // 1 MB, L2-resident

// ---------------- helpers ----------------
__device__ __forceinline__ unsigned sw128(unsigned off) {
    return off ^ ((off >> 3) & 0x70);
}
__device__ __forceinline__ uint32_t h2u(__half2 h) {
    return *reinterpret_cast<uint32_t*>(&h);
}
__device__ __forceinline__ void cp16s(uint32_t dst, const void* src) {
    asm volatile("cp.async.cg.shared.global [%0], [%1], 16;" :: "r"(dst), "l"(src));
}
__device__ __forceinline__ void cp_commit() { asm volatile("cp.async.commit_group;"); }
__device__ __forceinline__ void cp_wait0()  { asm volatile("cp.async.wait_group 0;"); }

__device__ __forceinline__ void ldm4(uint32_t& r0, uint32_t& r1, uint32_t& r2,
                                     uint32_t& r3, uint32_t addr) {
    asm volatile("ldmatrix.sync.aligned.m8n8.x4.shared.b16 {%0,%1,%2,%3}, [%4];"
                 : "=r"(r0), "=r"(r1), "=r"(r2), "=r"(r3) : "r"(addr));
}
__device__ __forceinline__ void mma16816(float* d, const uint32_t* a, const uint32_t* b) {
    asm volatile(
        "mma.sync.aligned.m16n8k16.row.col.f32.f16.f16.f32 "
        "{%0,%1,%2,%3}, {%4,%5,%6,%7}, {%8,%9}, {%0,%1,%2,%3};"
        : "+f"(d[0]), "+f"(d[1]), "+f"(d[2]), "+f"(d[3])
        : "r"(a[0]), "r"(a[1]), "r"(a[2]), "r"(a[3]), "r"(b[0]), "r"(b[1]));
}

// ---------------- prologue: fp16 2-split of (gate_w * 64), SW128, per chunk ----------------
__global__ void prep_w(const float* __restrict__ gw) {
    int idx = blockIdx.x * blockDim.x + threadIdx.x;   // 64c * 64e * 32kp = 131072
    int kp = idx & 31;
    int e  = (idx >> 5) & 63;
    int c  = idx >> 11;
    float2 v = *reinterpret_cast<const float2*>(&gw[(size_t)e * HDIM + c * HC + kp * 2]);
    float ax = v.x * WSCALE, ay = v.y * WSCALE;
    unsigned off = sw128((unsigned)(e * 128 + kp * 4));
    unsigned char* base = g_w_sw + (size_t)c * W_CHUNK_BYTES;
    __half2 h1 = __floats2half2_rn(ax, ay);
    *reinterpret_cast<uint32_t*>(base + off) = h2u(h1);
    float2 f1 = __half22float2(h1);
    __half2 h2 = __floats2half2_rn(ax - f1.x, ay - f1.y);
    *reinterpret_cast<uint32_t*>(base + B_SPLIT + off) = h2u(h2);
}

// ---------------- x staging ----------------
__device__ __forceinline__ void load_v(float4* v, const float* __restrict__ x,
                                       int tok0, int k0, int kq, int rowbase) {
    #pragma unroll
    for (int i = 0; i < 8; ++i)
        v[i] = *reinterpret_cast<const float4*>(
            &x[(size_t)(tok0 + rowbase + 16 * i) * HDIM + k0 + kq * 4]);
}
__device__ __forceinline__ void stage_x(unsigned char* buf, const float4* v,
                                        int kq, int rowbase) {
    #pragma unroll
    for (int i = 0; i < 8; ++i) {
        int r = rowbase + 16 * i;
        unsigned off = sw128((unsigned)(r * 128 + kq * 8));
        __half2 h1a = __floats2half2_rn(v[i].x, v[i].y);
        __half2 h1b = __floats2half2_rn(v[i].z, v[i].w);
        *reinterpret_cast<uint2*>(buf + off) = make_uint2(h2u(h1a), h2u(h1b));
        float2 f1a = __half22float2(h1a);
        float2 f1b = __half22float2(h1b);
        __half2 h2a = __floats2half2_rn(v[i].x - f1a.x, v[i].y - f1a.y);
        __half2 h2b = __floats2half2_rn(v[i].z - f1b.x, v[i].w - f1b.y);
        *reinterpret_cast<uint2*>(buf + A_SPLIT + off) = make_uint2(h2u(h2a), h2u(h2b));
    }
}

// ---------------- main fused router ----------------
extern __shared__ unsigned char smem_raw[];

__global__ __launch_bounds__(NTHREADS, 1)
void router_kernel(const float* __restrict__ x, float* __restrict__ out, int T) {
    const int tid  = threadIdx.x;
    const int lane = tid & 31;
    const int warp = tid >> 5;
    const int tok0 = blockIdx.x * TOK_PER_BLK;
    const uint32_t sb = (uint32_t)__cvta_generic_to_shared(smem_raw);

    // staging coords (all threads)
    const int kq      = tid & 15;
    const int rowbase = tid >> 4;
    float4 v[8];

    // consumer coords: warp covers m32 x n32 quadrant
    const int mbase = (warp & 3) * 32;
    const int nbase = (warp >> 2) * 32;
    const int rl    = lane & 15;
    const int cb    = lane >> 4;
    const int arx   = rl & 7;
    const int browl = (lane & 7) + ((lane & 16) >> 1);
    const int bcb   = (lane >> 3) & 1;
    const int bxor  = lane & 7;

    float acc[2][4][4];
    #pragma unroll
    for (int mt = 0; mt < 2; ++mt)
        #pragma unroll
        for (int nt = 0; nt < 4; ++nt)
            #pragma unroll
            for (int r = 0; r < 4; ++r) acc[mt][nt][r] = 0.f;

    // ---- prologue: stage chunk 0, prefetch chunk 1 LDG ----
    load_v(v, x, tok0, 0, kq, rowbase);
    #pragma unroll
    for (int i = 0; i < 4; ++i) {
        int lin = i * NTHREADS + tid;
        cp16s(sb + A_REGION + lin * 16, g_w_sw + lin * 16);
    }
    cp_commit();
    stage_x(smem_raw, v, kq, rowbase);
    load_v(v, x, tok0, HC, kq, rowbase);
    cp_wait0();
    __syncthreads();

    for (int c = 0; c < NCHUNKS; ++c) {
        // ---- stage chunk c+1 into the other buffer ----
        if (c + 1 < NCHUNKS) {
            unsigned char* nbuf = smem_raw + ((c + 1) & 1) * BUF_BYTES;
            const uint32_t nbufu = sb + ((c + 1) & 1) * BUF_BYTES;
            const unsigned char* src = g_w_sw + (size_t)(c + 1) * W_CHUNK_BYTES;
            #pragma unroll
            for (int i = 0; i < 4; ++i) {
                int lin = i * NTHREADS + tid;
                cp16s(nbufu + A_REGION + lin * 16, src + lin * 16);
            }
            cp_commit();
            stage_x(nbuf, v, kq, rowbase);
        }
        if (c + 2 < NCHUNKS)
            load_v(v, x, tok0, (c + 2) * HC, kq, rowbase);

        // ---- compute chunk c: 4 ksteps x 3 fp16-split products ----
        const uint32_t Ab = sb + (c & 1) * BUF_BYTES;
        const uint32_t Bb = Ab + A_REGION;
        const uint32_t a_row = Ab + (mbase + rl) * 128;
        const uint32_t b_row = Bb + (nbase + browl) * 128;
        #pragma unroll
        for (int ks = 0; ks < 4; ++ks) {
            uint32_t bf[2][8];
            const uint32_t bcol = (uint32_t)(((2 * ks + bcb) ^ bxor) * 16);
            #pragma unroll
            for (int s = 0; s < 2; ++s) {
                ldm4(bf[s][0], bf[s][1], bf[s][2], bf[s][3],
                     b_row + s * B_SPLIT + bcol);
                ldm4(bf[s][4], bf[s][5], bf[s][6], bf[s][7],
                     b_row + s * B_SPLIT + 2048 + bcol);
            }
            uint32_t af[2][2][4];
            const uint32_t acol = (uint32_t)(((2 * ks + cb) ^ arx) * 16);
            #pragma unroll
            for (int s = 0; s < 2; ++s)
                #pragma unroll
                for (int mt = 0; mt < 2; ++mt)
                    ldm4(af[s][mt][0], af[s][mt][1], af[s][mt][2], af[s][mt][3],
                         a_row + s * A_SPLIT + mt * 2048 + acol);
            // products: x1*w1, x1*w2, x2*w1
            #pragma unroll
            for (int p = 0; p < 3; ++p) {
                const int sa = (p == 2) ? 1 : 0;
                const int sbi = (p == 1) ? 1 : 0;
                #pragma unroll
                for (int mt = 0; mt < 2; ++mt)
                    #pragma unroll
                    for (int nt = 0; nt < 4; ++nt)
                        mma16816(acc[mt][nt], af[sa][mt], &bf[sbi][nt * 2]);
            }
        }
        cp_wait0();
        __syncthreads();
    }

    // ---- epilogue: descaled logits -> smem [128][68] ----
    float* ls = reinterpret_cast<float*>(smem_raw);
    #pragma unroll
    for (int mt = 0; mt < 2; ++mt) {
        int row0 = mbase + mt * 16 + (lane >> 2);
        #pragma unroll
        for (int nt = 0; nt < 4; ++nt) {
            int col = nbase + nt * 8 + (lane & 3) * 2;
            *reinterpret_cast<float2*>(&ls[row0 * 68 + col]) =
                make_float2(acc[mt][nt][0] * INV_WSCALE, acc[mt][nt][1] * INV_WSCALE);
            *reinterpret_cast<float2*>(&ls[(row0 + 8) * 68 + col]) =
                make_float2(acc[mt][nt][2] * INV_WSCALE, acc[mt][nt][3] * INV_WSCALE);
        }
    }
    __syncthreads();

    // one thread per token: top-2 + softmax scores + z partial
    float zsum = 0.f;
    if (tid < 128) {
        const float* row = &ls[tid * 68];
        float m = -3.402823466e38f; int i1 = 0;
        #pragma unroll 8
        for (int e = 0; e < EXP; ++e) {
            float vv = row[e];
            if (vv > m) { m = vv; i1 = e; }
        }
        float m2 = -3.402823466e38f; int i2 = 0;
        #pragma unroll 8
        for (int e = 0; e < EXP; ++e) {
            if (e == i1) continue;
            float vv = row[e];
            if (vv > m2) { m2 = vv; i2 = e; }
        }
        float Z = 0.f;
        #pragma unroll 8
        for (int e = 0; e < EXP; ++e) {
            float vv = row[e];
            Z += expf(vv - m);
            zsum += vv * vv;
        }
        int g = tok0 + tid;
        out[2 * g]     = (float)i1;
        out[2 * g + 1] = (float)i2;
        out[2 * T + 2 * g]     = 1.0f / Z;
        out[2 * T + 2 * g + 1] = expf(m2 - m) / Z;
    }

    // deterministic block reduce of z partial
    __shared__ float zred[NTHREADS];
    __shared__ unsigned int s_last;
    zred[tid] = zsum;
    __syncthreads();
    #pragma unroll
    for (int s = NTHREADS / 2; s > 0; s >>= 1) {
        if (tid < s) zred[tid] += zred[tid + s];
        __syncthreads();
    }
    if (tid == 0) {
        g_partials[blockIdx.x] = zred[0];
        __threadfence();
        unsigned prev = atomicAdd(&g_done, 1u);
        s_last = (prev == gridDim.x - 1) ? 1u : 0u;
    }
    __syncthreads();

    // last block finalizes (deterministic fixed-order tree over g_partials)
    if (s_last) {
        __threadfence();
        float pv = (tid < (int)gridDim.x) ? g_partials[tid] : 0.f;
        zred[tid] = pv;
        __syncthreads();
        #pragma unroll
        for (int s = NTHREADS / 2; s > 0; s >>= 1) {
            if (tid < s) zred[tid] += zred[tid + s];
            __syncthreads();
        }
        if (tid == 0) {
            out[4 * T]     = 0.0f;                       // aux_loss
            out[4 * T + 1] = zred[0] / (float)(T * EXP); // z_loss
            g_done = 0;                                  // reset for graph replay
        }
    }
}

extern "C" void kernel_launch(void* const* d_in, const int* in_sizes, int n_in,
                              void* d_out, int out_size) {
    const float* x  = (const float*)d_in[0];
    const float* gw = (const float*)d_in[1];
    float* out = (float*)d_out;

    int T = in_sizes[0] / HDIM;            // 16384
    int blocks = T / TOK_PER_BLK;          // 128

    cudaFuncSetAttribute(router_kernel,
                         cudaFuncAttributeMaxDynamicSharedMemorySize, SMEM_TOTAL);

    prep_w<<<512, 256>>>(gw);
    router_kernel<<<blocks, NTHREADS, SMEM_TOTAL>>>(x, out, T);
}